// round 12
// baseline (speedup 1.0000x reference)
#include <cuda_runtime.h>

#define T_STEPS 8192
#define MDIM    1024
#define INDIM   1024
#define XCOLS   5120
#define NCTA    128
#define NTHR    256
#define CELLS   8      // memory cells owned per CTA (1024/128)

// ---------------- scratch (static device globals; no allocation) -------------
__device__ float    g_xproj[(size_t)T_STEPS * XCOLS];   // 160 MB
__device__ float    g_h[MDIM];                           // h broadcast payload
__device__ float    g_a[MDIM];                           // a broadcast payload
__device__ __align__(128) unsigned g_flagA[NCTA];        // per-CTA monotonic tags (a)
__device__ __align__(128) unsigned g_flagH[NCTA];        // per-CTA monotonic tags (h)
__device__ unsigned g_epoch;                             // completed scan launches

// ---- flag helpers --------------------------------------------------------------
__device__ __forceinline__ unsigned ld_acq(const unsigned* p) {
    unsigned v;
    asm volatile("ld.acquire.gpu.global.u32 %0, [%1];" : "=r"(v) : "l"(p) : "memory");
    return v;
}
__device__ __forceinline__ void st_rel(unsigned* p, unsigned v) {
    asm volatile("st.release.gpu.global.u32 [%0], %1;" :: "l"(p), "r"(v) : "memory");
}
// Warp-collective: spin until all 128 flags >= tg. 4 coalesced line-loads/lane.
__device__ __forceinline__ void spin128(const unsigned* fl, unsigned tg, int lane) {
    for (;;) {
        unsigned a = ld_acq(fl + lane);
        unsigned b = ld_acq(fl + lane + 32);
        unsigned c = ld_acq(fl + lane + 64);
        unsigned d = ld_acq(fl + lane + 96);
        bool ok = (a >= tg) && (b >= tg) && (c >= tg) && (d >= tg);
        if (__all_sync(0xffffffffu, ok)) break;
    }
}

// ---- XLA-matched transcendentals ---------------------------------------------
__device__ __forceinline__ float xla_tanh(float x) {
    float xc = fminf(fmaxf(x, -9.0f), 9.0f);
    float x2 = xc * xc;
    float p = fmaf(x2, -2.76076847742355e-16f, 2.00018790482477e-13f);
    p = fmaf(x2, p, -8.60467152213735e-11f);
    p = fmaf(x2, p,  5.12229709037114e-08f);
    p = fmaf(x2, p,  1.48572235717979e-05f);
    p = fmaf(x2, p,  6.37261928875436e-04f);
    p = fmaf(x2, p,  4.89352455891786e-03f);
    float num = __fmul_rn(xc, p);
    float q = fmaf(x2, 1.19825839466702e-06f, 1.18534705686654e-04f);
    q = fmaf(x2, q, 2.26843463243900e-03f);
    q = fmaf(x2, q, 4.89352518554385e-03f);
    return (fabsf(x) < 4.0e-4f) ? x : __fdiv_rn(num, q);
}
__device__ __forceinline__ float xla_sigmoid(float x) {
    float e;
    asm("ex2.approx.f32 %0, %1;" : "=f"(e) : "f"(-x * 1.4426950408889634f));
    return __fdiv_rn(1.0f, __fadd_rn(1.0f, e));
}

// ---------------- Kernel 1: xproj = inputs @ Wx^T + bx  (NT SGEMM, fp32) -----
__global__ void __launch_bounds__(256) xproj_gemm(
    const float* __restrict__ A,
    const float* __restrict__ B,
    const float* __restrict__ bias)
{
    __shared__ float As[8][128];
    __shared__ float Bs[8][128];

    int tid = threadIdx.x;
    int tx  = tid & 15, ty = tid >> 4;
    int m0  = blockIdx.y * 128, n0 = blockIdx.x * 128;
    int lrow = tid >> 1, lk = (tid & 1) * 4;

    const float* Ap = A + (size_t)(m0 + lrow) * INDIM + lk;
    const float* Bp = B + (size_t)(n0 + lrow) * INDIM + lk;

    float acc[8][8];
#pragma unroll
    for (int i = 0; i < 8; i++)
#pragma unroll
        for (int j = 0; j < 8; j++) acc[i][j] = 0.0f;

    for (int k0 = 0; k0 < INDIM; k0 += 8) {
        float4 av = *(const float4*)(Ap + k0);
        float4 bv = *(const float4*)(Bp + k0);
        As[lk + 0][lrow] = av.x; As[lk + 1][lrow] = av.y;
        As[lk + 2][lrow] = av.z; As[lk + 3][lrow] = av.w;
        Bs[lk + 0][lrow] = bv.x; Bs[lk + 1][lrow] = bv.y;
        Bs[lk + 2][lrow] = bv.z; Bs[lk + 3][lrow] = bv.w;
        __syncthreads();
#pragma unroll
        for (int kk = 0; kk < 8; kk++) {
            float a[8], b[8];
            *(float4*)&a[0] = *(const float4*)&As[kk][ty * 8];
            *(float4*)&a[4] = *(const float4*)&As[kk][ty * 8 + 4];
            *(float4*)&b[0] = *(const float4*)&Bs[kk][tx * 8];
            *(float4*)&b[4] = *(const float4*)&Bs[kk][tx * 8 + 4];
#pragma unroll
            for (int i = 0; i < 8; i++)
#pragma unroll
                for (int j = 0; j < 8; j++) acc[i][j] += a[i] * b[j];
        }
        __syncthreads();
    }

    float bb[8];
#pragma unroll
    for (int j = 0; j < 8; j++) bb[j] = bias[n0 + tx * 8 + j];
#pragma unroll
    for (int i = 0; i < 8; i++) {
        float* crow = g_xproj + (size_t)(m0 + ty * 8 + i) * XCOLS + n0 + tx * 8;
        float4 v0 = make_float4(__fadd_rn(acc[i][0], bb[0]), __fadd_rn(acc[i][1], bb[1]),
                                __fadd_rn(acc[i][2], bb[2]), __fadd_rn(acc[i][3], bb[3]));
        float4 v1 = make_float4(__fadd_rn(acc[i][4], bb[4]), __fadd_rn(acc[i][5], bb[5]),
                                __fadd_rn(acc[i][6], bb[6]), __fadd_rn(acc[i][7], bb[7]));
        *(float4*)crow       = v0;
        *(float4*)(crow + 4) = v1;
    }
}

// ---------------- Kernel 2: persistent recurrent scan ------------------------
// 128 CTAs x 256 threads. Warp w (0..7) owns Wh slice rows 4w..4w+3
// (row s = gate*8 + cell) and Wm row w. Sync: per-CTA flag words, warp-0
// detection (4 lines), release/acquire; payload via __stcg/__ldcg.
__global__ void __launch_bounds__(NTHR, 1) ulstm_scan(
    const float* __restrict__ Wh, const float* __restrict__ bh,
    const float* __restrict__ Wm, const float* __restrict__ bm,
    float* __restrict__ out)
{
    __shared__ __align__(16) float h_s[MDIM];
    __shared__ __align__(16) float a_s[MDIM];
    __shared__ float hp_s[32];
    __shared__ float gate_s[32];   // i(0..7) o(8..15) z(16..23) f(24..31)
    __shared__ float gu_s[CELLS];
    __shared__ float tc_s[CELLS];  // tanh(c) carried from previous step
    __shared__ float c_s[CELLS];
    __shared__ float bh_s[32];
    __shared__ float bm_s[CELLS];

    const int tid = threadIdx.x;
    const int w   = tid >> 5;
    const int l   = tid & 31;
    const int cta = blockIdx.x;

    const unsigned base = (*((volatile unsigned*)&g_epoch)) * 16384u;  // monotonic tags

    // ---- weights into registers (persist across all 8192 steps) ----
    float4 wa[4][8];
#pragma unroll
    for (int r = 0; r < 4; r++) {
        int s   = 4 * w + r;
        int row = (s >> 3) * MDIM + cta * CELLS + (s & 7);
        const float4* src = (const float4*)(Wh + (size_t)row * MDIM);
#pragma unroll
        for (int c4 = 0; c4 < 8; c4++) wa[r][c4] = src[c4 * 32 + l];
    }
    float4 wmr[8];
    {
        int row = cta * CELLS + w;
        const float4* src = (const float4*)(Wm + (size_t)row * MDIM);
#pragma unroll
        for (int c4 = 0; c4 < 8; c4++) wmr[c4] = src[c4 * 32 + l];
    }
    if (tid < 32) bh_s[tid] = bh[(tid >> 3) * MDIM + cta * CELLS + (tid & 7)];
    if (tid < CELLS) { bm_s[tid] = bm[cta * CELLS + tid]; c_s[tid] = 0.0f; tc_s[tid] = 0.0f; }
    __syncthreads();

    // ---- xproj prefetch double-buffer (warp 0), row 0 prologue ----
    float xg_c = 0.f, ux_c = 0.f;
    if (tid < 32) {
        const float* xr = g_xproj + (tid >> 3) * MDIM + cta * CELLS + (tid & 7);
        xg_c = __ldcg(xr);
        if (tid < 8) ux_c = __ldcg(xr + 4 * MDIM);
    }

    for (int t = 0; t < T_STEPS; t++) {
        // issue next step's xproj loads now (fully hidden behind this step)
        float xg_n = 0.f, ux_n = 0.f;
        if (tid < 32) {
            int tn = (t + 1 < T_STEPS) ? t + 1 : t;
            const float* xr = g_xproj + (size_t)tn * XCOLS + (tid >> 3) * MDIM + cta * CELLS + (tid & 7);
            xg_n = __ldcg(xr);
            if (tid < 8) ux_n = __ldcg(xr + 4 * MDIM);
        }

        // ---------- h exchange + Phase A: hp = Wh @ h + bh ----------
        if (t > 0) {
            if (w == 0) spin128(g_flagH, base + (unsigned)t, l);
            __syncthreads();
            ((float4*)h_s)[tid] = __ldcg((const float4*)g_h + tid);
            __syncthreads();
            float acc0 = 0.f, acc1 = 0.f, acc2 = 0.f, acc3 = 0.f;
#pragma unroll
            for (int c4 = 0; c4 < 8; c4++) {
                float4 hv = ((const float4*)h_s)[c4 * 32 + l];
                acc0 += wa[0][c4].x * hv.x + wa[0][c4].y * hv.y + wa[0][c4].z * hv.z + wa[0][c4].w * hv.w;
                acc1 += wa[1][c4].x * hv.x + wa[1][c4].y * hv.y + wa[1][c4].z * hv.z + wa[1][c4].w * hv.w;
                acc2 += wa[2][c4].x * hv.x + wa[2][c4].y * hv.y + wa[2][c4].z * hv.z + wa[2][c4].w * hv.w;
                acc3 += wa[3][c4].x * hv.x + wa[3][c4].y * hv.y + wa[3][c4].z * hv.z + wa[3][c4].w * hv.w;
            }
#pragma unroll
            for (int off = 16; off > 0; off >>= 1) {
                acc0 += __shfl_xor_sync(0xffffffffu, acc0, off);
                acc1 += __shfl_xor_sync(0xffffffffu, acc1, off);
                acc2 += __shfl_xor_sync(0xffffffffu, acc2, off);
                acc3 += __shfl_xor_sync(0xffffffffu, acc3, off);
            }
            if (l == 0) {
                hp_s[4 * w + 0] = __fadd_rn(acc0, bh_s[4 * w + 0]);
                hp_s[4 * w + 1] = __fadd_rn(acc1, bh_s[4 * w + 1]);
                hp_s[4 * w + 2] = __fadd_rn(acc2, bh_s[4 * w + 2]);
                hp_s[4 * w + 3] = __fadd_rn(acc3, bh_s[4 * w + 3]);
            }
        } else {
            if (tid < 32) hp_s[tid] = bh_s[tid];   // h0 = 0 -> hp = bh
        }
        __syncthreads();

        // ---------- gates (warp 0) + a publish + a detect ----------
        const unsigned tgA = base + (unsigned)t + 1u;
        if (w == 0) {
            if (l < 8) gu_s[l] = ux_c;
            float s = xla_sigmoid(__fadd_rn(xg_c, hp_s[l]));
            gate_s[l] = s;
            __syncwarp();
            if (l < 8) __stcg(&g_a[cta * CELLS + l], __fmul_rn(gate_s[16 + l], tc_s[l]));
            __syncwarp();
            if (l == 0) st_rel(&g_flagA[cta], tgA);
            spin128(g_flagA, tgA, l);
        }
        __syncthreads();
        ((float4*)a_s)[tid] = __ldcg((const float4*)g_a + tid);
        __syncthreads();

        // ---------- Phase B: u = tanh(ux + Wm@a + bm); state update ----------
        float acc = 0.f;
#pragma unroll
        for (int c4 = 0; c4 < 8; c4++) {
            float4 av = ((const float4*)a_s)[c4 * 32 + l];
            acc += wmr[c4].x * av.x + wmr[c4].y * av.y + wmr[c4].z * av.z + wmr[c4].w * av.w;
        }
#pragma unroll
        for (int off = 16; off > 0; off >>= 1)
            acc += __shfl_xor_sync(0xffffffffu, acc, off);

        if (l == 0) {
            float u  = xla_tanh(__fadd_rn(__fadd_rn(gu_s[w], acc), bm_s[w]));
            float c2 = __fadd_rn(__fmul_rn(gate_s[w], u), __fmul_rn(gate_s[24 + w], c_s[w]));
            float th = xla_tanh(c2);
            float h2 = __fmul_rn(gate_s[8 + w], th);
            c_s[w]  = c2;
            tc_s[w] = th;    // reused next step: a = z * tanh(c)
            if (t == T_STEPS - 1) {
                out[cta * CELLS + w]        = c2;
                out[MDIM + cta * CELLS + w] = h2;
            } else {
                __stcg(&g_h[cta * CELLS + w], h2);
            }
        }
        __syncthreads();   // all 8 warps' h stores before the release flag
        if (t < T_STEPS - 1 && tid == 0) st_rel(&g_flagH[cta], base + (unsigned)t + 1u);

        xg_c = xg_n; ux_c = ux_n;   // rotate prefetch buffer
    }

    // one epoch bump per launch (every CTA read g_epoch at start; replays are
    // stream-ordered, and tags stay monotonic with no resets)
    if (cta == 0 && tid == 0)
        asm volatile("red.relaxed.gpu.global.add.u32 [%0], 1;" :: "l"(&g_epoch) : "memory");
}

// ---------------- launch ------------------------------------------------------
extern "C" void kernel_launch(void* const* d_in, const int* in_sizes, int n_in,
                              void* d_out, int out_size)
{
    const float* inputs = (const float*)d_in[0];
    const float* Wx     = (const float*)d_in[1];
    const float* bx     = (const float*)d_in[2];
    const float* Wh     = (const float*)d_in[3];
    const float* bh     = (const float*)d_in[4];
    const float* Wm     = (const float*)d_in[5];
    const float* bm     = (const float*)d_in[6];
    float* out = (float*)d_out;

    dim3 ggrid(XCOLS / 128, T_STEPS / 128);   // (40, 64)
    xproj_gemm<<<ggrid, 256>>>(inputs, Wx, bx);

    ulstm_scan<<<NCTA, NTHR>>>(Wh, bh, Wm, bm, out);
}

// round 14
// speedup vs baseline: 1.9925x; 1.9925x over previous
#include <cuda_runtime.h>

#define T_STEPS 8192
#define MDIM    1024
#define INDIM   1024
#define XCOLS   5120
#define NCTA    128
#define NTHR    256
#define CELLS   8      // memory cells owned per CTA (1024/128)

// ---------------- scratch (static device globals; no allocation) -------------
__device__ float    g_xproj[(size_t)T_STEPS * XCOLS];   // 160 MB
__device__ float    g_h[MDIM];                           // h broadcast payload
__device__ float    g_a[MDIM];                           // a broadcast payload
// 8 split counters per barrier, each on its own 128B line; accumulate forever.
__device__ __align__(128) unsigned g_ctrA[8 * 32];
__device__ __align__(128) unsigned g_ctrH[8 * 32];
__device__ unsigned g_epoch;                             // completed scan launches

// ---- sync helpers --------------------------------------------------------------
__device__ __forceinline__ unsigned ld_rlx(const unsigned* p) {
    unsigned v;
    asm volatile("ld.relaxed.gpu.global.u32 %0, [%1];" : "=r"(v) : "l"(p) : "memory");
    return v;
}
// Grid barrier: arrival = fire-and-forget release-RED to one of 8 split
// counters (16 CTAs per address). Detection = tid0 only: 8 independent
// relaxed loads (parallel, one L2 RT per round), sum vs monotonic target,
// then one acquire fence to pair with the releases.
__device__ __forceinline__ void gbar(unsigned* ctr, unsigned target) {
    __syncthreads();
    if (threadIdx.x == 0) {
        asm volatile("red.release.gpu.global.add.u32 [%0], 1;"
                     :: "l"(ctr + (blockIdx.x & 7) * 32) : "memory");
        unsigned s;
        do {
            unsigned v0 = ld_rlx(ctr +   0), v1 = ld_rlx(ctr +  32);
            unsigned v2 = ld_rlx(ctr +  64), v3 = ld_rlx(ctr +  96);
            unsigned v4 = ld_rlx(ctr + 128), v5 = ld_rlx(ctr + 160);
            unsigned v6 = ld_rlx(ctr + 192), v7 = ld_rlx(ctr + 224);
            s = v0 + v1 + v2 + v3 + v4 + v5 + v6 + v7;
        } while (s < target);
        asm volatile("fence.acq_rel.gpu;" ::: "memory");
    }
    __syncthreads();
}

// ---- XLA-matched transcendentals ---------------------------------------------
__device__ __forceinline__ float xla_tanh(float x) {
    float xc = fminf(fmaxf(x, -9.0f), 9.0f);
    float x2 = xc * xc;
    float p = fmaf(x2, -2.76076847742355e-16f, 2.00018790482477e-13f);
    p = fmaf(x2, p, -8.60467152213735e-11f);
    p = fmaf(x2, p,  5.12229709037114e-08f);
    p = fmaf(x2, p,  1.48572235717979e-05f);
    p = fmaf(x2, p,  6.37261928875436e-04f);
    p = fmaf(x2, p,  4.89352455891786e-03f);
    float num = __fmul_rn(xc, p);
    float q = fmaf(x2, 1.19825839466702e-06f, 1.18534705686654e-04f);
    q = fmaf(x2, q, 2.26843463243900e-03f);
    q = fmaf(x2, q, 4.89352518554385e-03f);
    return (fabsf(x) < 4.0e-4f) ? x : __fdiv_rn(num, q);
}
__device__ __forceinline__ float xla_sigmoid(float x) {
    float e;
    asm("ex2.approx.f32 %0, %1;" : "=f"(e) : "f"(-x * 1.4426950408889634f));
    return __fdiv_rn(1.0f, __fadd_rn(1.0f, e));
}

// ---------------- Kernel 1: xproj = inputs @ Wx^T + bx  (NT SGEMM, fp32) -----
__global__ void __launch_bounds__(256) xproj_gemm(
    const float* __restrict__ A,
    const float* __restrict__ B,
    const float* __restrict__ bias)
{
    __shared__ float As[8][128];
    __shared__ float Bs[8][128];

    int tid = threadIdx.x;
    int tx  = tid & 15, ty = tid >> 4;
    int m0  = blockIdx.y * 128, n0 = blockIdx.x * 128;
    int lrow = tid >> 1, lk = (tid & 1) * 4;

    const float* Ap = A + (size_t)(m0 + lrow) * INDIM + lk;
    const float* Bp = B + (size_t)(n0 + lrow) * INDIM + lk;

    float acc[8][8];
#pragma unroll
    for (int i = 0; i < 8; i++)
#pragma unroll
        for (int j = 0; j < 8; j++) acc[i][j] = 0.0f;

    for (int k0 = 0; k0 < INDIM; k0 += 8) {
        float4 av = *(const float4*)(Ap + k0);
        float4 bv = *(const float4*)(Bp + k0);
        As[lk + 0][lrow] = av.x; As[lk + 1][lrow] = av.y;
        As[lk + 2][lrow] = av.z; As[lk + 3][lrow] = av.w;
        Bs[lk + 0][lrow] = bv.x; Bs[lk + 1][lrow] = bv.y;
        Bs[lk + 2][lrow] = bv.z; Bs[lk + 3][lrow] = bv.w;
        __syncthreads();
#pragma unroll
        for (int kk = 0; kk < 8; kk++) {
            float a[8], b[8];
            *(float4*)&a[0] = *(const float4*)&As[kk][ty * 8];
            *(float4*)&a[4] = *(const float4*)&As[kk][ty * 8 + 4];
            *(float4*)&b[0] = *(const float4*)&Bs[kk][tx * 8];
            *(float4*)&b[4] = *(const float4*)&Bs[kk][tx * 8 + 4];
#pragma unroll
            for (int i = 0; i < 8; i++)
#pragma unroll
                for (int j = 0; j < 8; j++) acc[i][j] += a[i] * b[j];
        }
        __syncthreads();
    }

    float bb[8];
#pragma unroll
    for (int j = 0; j < 8; j++) bb[j] = bias[n0 + tx * 8 + j];
#pragma unroll
    for (int i = 0; i < 8; i++) {
        float* crow = g_xproj + (size_t)(m0 + ty * 8 + i) * XCOLS + n0 + tx * 8;
        float4 v0 = make_float4(__fadd_rn(acc[i][0], bb[0]), __fadd_rn(acc[i][1], bb[1]),
                                __fadd_rn(acc[i][2], bb[2]), __fadd_rn(acc[i][3], bb[3]));
        float4 v1 = make_float4(__fadd_rn(acc[i][4], bb[4]), __fadd_rn(acc[i][5], bb[5]),
                                __fadd_rn(acc[i][6], bb[6]), __fadd_rn(acc[i][7], bb[7]));
        *(float4*)crow       = v0;
        *(float4*)(crow + 4) = v1;
    }
}

// ---------------- Kernel 2: persistent recurrent scan ------------------------
// 128 CTAs x 256 threads (proven R7 structure). Warp w (0..7) owns Wh slice
// rows 4w..4w+3 (row s = gate*8 + cell) and Wm row w.
__global__ void __launch_bounds__(NTHR, 1) ulstm_scan(
    const float* __restrict__ Wh, const float* __restrict__ bh,
    const float* __restrict__ Wm, const float* __restrict__ bm,
    float* __restrict__ out)
{
    __shared__ __align__(16) float h_s[MDIM];
    __shared__ __align__(16) float a_s[MDIM];
    __shared__ float hp_s[32];
    __shared__ float gate_s[32];   // i(0..7) o(8..15) z(16..23) f(24..31)
    __shared__ float gu_s[CELLS];
    __shared__ float tc_s[CELLS];  // tanh(c) carried from previous step
    __shared__ float c_s[CELLS];
    __shared__ float bh_s[32];
    __shared__ float bm_s[CELLS];

    const int tid = threadIdx.x;
    const int w   = tid >> 5;
    const int l   = tid & 31;
    const int cta = blockIdx.x;

    // monotonic targets: after step t's barrier, counter-sum = epoch*T*128 + (t+1)*128
    const unsigned ebase = (*((volatile unsigned*)&g_epoch)) << 20;   // epoch*8192*128

    // ---- weights into registers (persist across all 8192 steps) ----
    float4 wa[4][8];
#pragma unroll
    for (int r = 0; r < 4; r++) {
        int s   = 4 * w + r;
        int row = (s >> 3) * MDIM + cta * CELLS + (s & 7);
        const float4* src = (const float4*)(Wh + (size_t)row * MDIM);
#pragma unroll
        for (int c4 = 0; c4 < 8; c4++) wa[r][c4] = src[c4 * 32 + l];
    }
    float4 wmr[8];
    {
        int row = cta * CELLS + w;
        const float4* src = (const float4*)(Wm + (size_t)row * MDIM);
#pragma unroll
        for (int c4 = 0; c4 < 8; c4++) wmr[c4] = src[c4 * 32 + l];
    }
    if (tid < 32) bh_s[tid] = bh[(tid >> 3) * MDIM + cta * CELLS + (tid & 7)];
    if (tid < CELLS) { bm_s[tid] = bm[cta * CELLS + tid]; c_s[tid] = 0.0f; tc_s[tid] = 0.0f; }
    __syncthreads();

    const float4* gh4 = (const float4*)g_h;
    const float4* ga4 = (const float4*)g_a;

    // ---- xproj prefetch double-buffer (warp 0), row 0 prologue ----
    float xg_c = 0.f, ux_c = 0.f;
    if (tid < 32) {
        const float* xr = g_xproj + (tid >> 3) * MDIM + cta * CELLS + (tid & 7);
        xg_c = __ldcg(xr);
        if (tid < 8) ux_c = __ldcg(xr + 4 * MDIM);
    }

    for (int t = 0; t < T_STEPS; t++) {
        // issue next step's xproj loads now (DRAM latency hidden behind this step)
        float xg_n = 0.f, ux_n = 0.f;
        if (tid < 32) {
            int tn = (t + 1 < T_STEPS) ? t + 1 : t;
            const float* xr = g_xproj + (size_t)tn * XCOLS + (tid >> 3) * MDIM + cta * CELLS + (tid & 7);
            xg_n = __ldcg(xr);
            if (tid < 8) ux_n = __ldcg(xr + 4 * MDIM);
        }

        // ---------- Phase A: hp = Wh @ h + bh (h-barrier was end of step t-1)
        if (t > 0) {
            ((float4*)h_s)[tid] = __ldcg(gh4 + tid);
            __syncthreads();
            float acc0 = 0.f, acc1 = 0.f, acc2 = 0.f, acc3 = 0.f;
#pragma unroll
            for (int c4 = 0; c4 < 8; c4++) {
                float4 hv = ((const float4*)h_s)[c4 * 32 + l];
                acc0 += wa[0][c4].x * hv.x + wa[0][c4].y * hv.y + wa[0][c4].z * hv.z + wa[0][c4].w * hv.w;
                acc1 += wa[1][c4].x * hv.x + wa[1][c4].y * hv.y + wa[1][c4].z * hv.z + wa[1][c4].w * hv.w;
                acc2 += wa[2][c4].x * hv.x + wa[2][c4].y * hv.y + wa[2][c4].z * hv.z + wa[2][c4].w * hv.w;
                acc3 += wa[3][c4].x * hv.x + wa[3][c4].y * hv.y + wa[3][c4].z * hv.z + wa[3][c4].w * hv.w;
            }
#pragma unroll
            for (int off = 16; off > 0; off >>= 1) {
                acc0 += __shfl_xor_sync(0xffffffffu, acc0, off);
                acc1 += __shfl_xor_sync(0xffffffffu, acc1, off);
                acc2 += __shfl_xor_sync(0xffffffffu, acc2, off);
                acc3 += __shfl_xor_sync(0xffffffffu, acc3, off);
            }
            if (l == 0) {
                hp_s[4 * w + 0] = __fadd_rn(acc0, bh_s[4 * w + 0]);
                hp_s[4 * w + 1] = __fadd_rn(acc1, bh_s[4 * w + 1]);
                hp_s[4 * w + 2] = __fadd_rn(acc2, bh_s[4 * w + 2]);
                hp_s[4 * w + 3] = __fadd_rn(acc3, bh_s[4 * w + 3]);
            }
        } else {
            if (tid < 32) hp_s[tid] = bh_s[tid];   // h0 = 0 -> hp = bh
        }
        __syncthreads();

        // ---------- gates (warp 0) + a publish; split-counter barrier --------
        const unsigned target = ebase + ((unsigned)(t + 1) << 7);
        if (tid < 32) {
            if (tid < 8) gu_s[tid] = ux_c;
            float s = xla_sigmoid(__fadd_rn(xg_c, hp_s[tid]));
            gate_s[tid] = s;
            __syncwarp();
            if (tid < 8)
                __stcg(&g_a[cta * CELLS + tid], __fmul_rn(gate_s[16 + tid], tc_s[tid]));
        }
        gbar(g_ctrA, target);

        // ---------- Phase B: u = tanh(ux + Wm@a + bm); state update ----------
        ((float4*)a_s)[tid] = __ldcg(ga4 + tid);
        __syncthreads();
        float acc = 0.f;
#pragma unroll
        for (int c4 = 0; c4 < 8; c4++) {
            float4 av = ((const float4*)a_s)[c4 * 32 + l];
            acc += wmr[c4].x * av.x + wmr[c4].y * av.y + wmr[c4].z * av.z + wmr[c4].w * av.w;
        }
#pragma unroll
        for (int off = 16; off > 0; off >>= 1)
            acc += __shfl_xor_sync(0xffffffffu, acc, off);

        if (l == 0) {
            float u  = xla_tanh(__fadd_rn(__fadd_rn(gu_s[w], acc), bm_s[w]));
            float c2 = __fadd_rn(__fmul_rn(gate_s[w], u), __fmul_rn(gate_s[24 + w], c_s[w]));
            float th = xla_tanh(c2);
            float h2 = __fmul_rn(gate_s[8 + w], th);
            c_s[w]  = c2;
            tc_s[w] = th;    // reused next step: a = z * tanh(c)
            if (t == T_STEPS - 1) {
                out[cta * CELLS + w]        = c2;
                out[MDIM + cta * CELLS + w] = h2;
            } else {
                __stcg(&g_h[cta * CELLS + w], h2);
            }
        }
        gbar(g_ctrH, target);   // uniform: fires every step (last one is harmless)

        xg_c = xg_n; ux_c = ux_n;   // rotate prefetch buffer
    }

    // one epoch bump per launch (every CTA read g_epoch before its first
    // barrier; replays are stream-ordered; counters stay monotonic, no resets)
    if (cta == 0 && tid == 0)
        asm volatile("red.relaxed.gpu.global.add.u32 [%0], 1;" :: "l"(&g_epoch) : "memory");
}

// ---------------- launch ------------------------------------------------------
extern "C" void kernel_launch(void* const* d_in, const int* in_sizes, int n_in,
                              void* d_out, int out_size)
{
    const float* inputs = (const float*)d_in[0];
    const float* Wx     = (const float*)d_in[1];
    const float* bx     = (const float*)d_in[2];
    const float* Wh     = (const float*)d_in[3];
    const float* bh     = (const float*)d_in[4];
    const float* Wm     = (const float*)d_in[5];
    const float* bm     = (const float*)d_in[6];
    float* out = (float*)d_out;

    dim3 ggrid(XCOLS / 128, T_STEPS / 128);   // (40, 64)
    xproj_gemm<<<ggrid, 256>>>(inputs, Wx, bx);

    ulstm_scan<<<NCTA, NTHR>>>(Wh, bh, Wm, bm, out);
}

// round 15
// speedup vs baseline: 2.0935x; 1.0507x over previous
#include <cuda_runtime.h>

#define T_STEPS 8192
#define MDIM    1024
#define INDIM   1024
#define XCOLS   5120
#define NCTA    128
#define NTHR    256
#define CELLS   8      // memory cells owned per CTA (1024/128)

// ---------------- scratch (static device globals; no allocation) -------------
__device__ float    g_xproj[(size_t)T_STEPS * XCOLS];   // 160 MB
__device__ float    g_h[MDIM];                           // h broadcast payload
__device__ float    g_a[MDIM];                           // a broadcast payload
// Rotating barrier counters: 8 slots per barrier, one 128B line each,
// accumulate forever (epoch-folded monotonic targets; no resets).
__device__ __align__(128) unsigned g_ctrA[8 * 32];
__device__ __align__(128) unsigned g_ctrH[8 * 32];
__device__ unsigned g_epoch;                             // completed scan launches

// ---- sync helpers --------------------------------------------------------------
__device__ __forceinline__ unsigned ld_acq(const unsigned* p) {
    unsigned v;
    asm volatile("ld.acquire.gpu.global.u32 %0, [%1];" : "=r"(v) : "l"(p) : "memory");
    return v;
}
__device__ __forceinline__ void red_rel(unsigned* p) {
    asm volatile("red.release.gpu.global.add.u32 [%0], 1;" :: "l"(p) : "memory");
}

// ---- XLA-matched transcendentals ---------------------------------------------
__device__ __forceinline__ float xla_tanh(float x) {
    float xc = fminf(fmaxf(x, -9.0f), 9.0f);
    float x2 = xc * xc;
    float p = fmaf(x2, -2.76076847742355e-16f, 2.00018790482477e-13f);
    p = fmaf(x2, p, -8.60467152213735e-11f);
    p = fmaf(x2, p,  5.12229709037114e-08f);
    p = fmaf(x2, p,  1.48572235717979e-05f);
    p = fmaf(x2, p,  6.37261928875436e-04f);
    p = fmaf(x2, p,  4.89352455891786e-03f);
    float num = __fmul_rn(xc, p);
    float q = fmaf(x2, 1.19825839466702e-06f, 1.18534705686654e-04f);
    q = fmaf(x2, q, 2.26843463243900e-03f);
    q = fmaf(x2, q, 4.89352518554385e-03f);
    return (fabsf(x) < 4.0e-4f) ? x : __fdiv_rn(num, q);
}
__device__ __forceinline__ float xla_sigmoid(float x) {
    float e;
    asm("ex2.approx.f32 %0, %1;" : "=f"(e) : "f"(-x * 1.4426950408889634f));
    return __fdiv_rn(1.0f, __fadd_rn(1.0f, e));
}

// ---------------- Kernel 1: xproj = inputs @ Wx^T + bx  (NT SGEMM, fp32) -----
__global__ void __launch_bounds__(256) xproj_gemm(
    const float* __restrict__ A,
    const float* __restrict__ B,
    const float* __restrict__ bias)
{
    __shared__ float As[8][128];
    __shared__ float Bs[8][128];

    int tid = threadIdx.x;
    int tx  = tid & 15, ty = tid >> 4;
    int m0  = blockIdx.y * 128, n0 = blockIdx.x * 128;
    int lrow = tid >> 1, lk = (tid & 1) * 4;

    const float* Ap = A + (size_t)(m0 + lrow) * INDIM + lk;
    const float* Bp = B + (size_t)(n0 + lrow) * INDIM + lk;

    float acc[8][8];
#pragma unroll
    for (int i = 0; i < 8; i++)
#pragma unroll
        for (int j = 0; j < 8; j++) acc[i][j] = 0.0f;

    for (int k0 = 0; k0 < INDIM; k0 += 8) {
        float4 av = *(const float4*)(Ap + k0);
        float4 bv = *(const float4*)(Bp + k0);
        As[lk + 0][lrow] = av.x; As[lk + 1][lrow] = av.y;
        As[lk + 2][lrow] = av.z; As[lk + 3][lrow] = av.w;
        Bs[lk + 0][lrow] = bv.x; Bs[lk + 1][lrow] = bv.y;
        Bs[lk + 2][lrow] = bv.z; Bs[lk + 3][lrow] = bv.w;
        __syncthreads();
#pragma unroll
        for (int kk = 0; kk < 8; kk++) {
            float a[8], b[8];
            *(float4*)&a[0] = *(const float4*)&As[kk][ty * 8];
            *(float4*)&a[4] = *(const float4*)&As[kk][ty * 8 + 4];
            *(float4*)&b[0] = *(const float4*)&Bs[kk][tx * 8];
            *(float4*)&b[4] = *(const float4*)&Bs[kk][tx * 8 + 4];
#pragma unroll
            for (int i = 0; i < 8; i++)
#pragma unroll
                for (int j = 0; j < 8; j++) acc[i][j] += a[i] * b[j];
        }
        __syncthreads();
    }

    float bb[8];
#pragma unroll
    for (int j = 0; j < 8; j++) bb[j] = bias[n0 + tx * 8 + j];
#pragma unroll
    for (int i = 0; i < 8; i++) {
        float* crow = g_xproj + (size_t)(m0 + ty * 8 + i) * XCOLS + n0 + tx * 8;
        float4 v0 = make_float4(__fadd_rn(acc[i][0], bb[0]), __fadd_rn(acc[i][1], bb[1]),
                                __fadd_rn(acc[i][2], bb[2]), __fadd_rn(acc[i][3], bb[3]));
        float4 v1 = make_float4(__fadd_rn(acc[i][4], bb[4]), __fadd_rn(acc[i][5], bb[5]),
                                __fadd_rn(acc[i][6], bb[6]), __fadd_rn(acc[i][7], bb[7]));
        *(float4*)crow       = v0;
        *(float4*)(crow + 4) = v1;
    }
}

// ---------------- Kernel 2: persistent recurrent scan ------------------------
// 128 CTAs x 256 threads (R7 structure). Warp w (0..7) owns Wh slice rows
// 4w..4w+3 (row s = gate*8 + cell, gate = s>>3, cell = s&7) and Wm row w.
// Gates are computed in-warp right after the reduce; warps 4-5 (z-gate rows)
// publish `a` immediately and fire the A-barrier arrival.
__global__ void __launch_bounds__(NTHR, 1) ulstm_scan(
    const float* __restrict__ Wh, const float* __restrict__ bh,
    const float* __restrict__ Wm, const float* __restrict__ bm,
    float* __restrict__ out)
{
    __shared__ __align__(16) float h_s[MDIM];
    __shared__ __align__(16) float a_s[MDIM];
    __shared__ float xg_s[32];     // this step's xproj gate inputs (i,o,z,f)
    __shared__ float gate_s[32];   // sigmoid outputs, indexed by row s (z unused)
    __shared__ float gu_s[CELLS];  // this step's ux
    __shared__ float tc_s[CELLS];  // tanh(c) carried from previous step
    __shared__ float c_s[CELLS];
    __shared__ float bh_s[32];
    __shared__ float bm_s[CELLS];

    const int tid = threadIdx.x;
    const int w   = tid >> 5;
    const int l   = tid & 31;
    const int cta = blockIdx.x;

    // epoch-folded monotonic targets: slot (t&7); per-launch uses per slot = 1024
    const unsigned epoch = *((volatile unsigned*)&g_epoch);

    // ---- weights into registers (persist across all 8192 steps) ----
    float4 wa[4][8];
#pragma unroll
    for (int r = 0; r < 4; r++) {
        int s   = 4 * w + r;
        int row = (s >> 3) * MDIM + cta * CELLS + (s & 7);
        const float4* src = (const float4*)(Wh + (size_t)row * MDIM);
#pragma unroll
        for (int c4 = 0; c4 < 8; c4++) wa[r][c4] = src[c4 * 32 + l];
    }
    float4 wmr[8];
    {
        int row = cta * CELLS + w;
        const float4* src = (const float4*)(Wm + (size_t)row * MDIM);
#pragma unroll
        for (int c4 = 0; c4 < 8; c4++) wmr[c4] = src[c4 * 32 + l];
    }
    if (tid < 32) bh_s[tid] = bh[(tid >> 3) * MDIM + cta * CELLS + (tid & 7)];
    if (tid < CELLS) { bm_s[tid] = bm[cta * CELLS + tid]; c_s[tid] = 0.0f; tc_s[tid] = 0.0f; }
    __syncthreads();

    const float4* gh4 = (const float4*)g_h;
    const float4* ga4 = (const float4*)g_a;

    // ---- xproj prefetch buffer (warp 0 registers), row 0 prologue ----
    float xg_c = 0.f, ux_c = 0.f;
    if (tid < 32) {
        const float* xr = g_xproj + (tid >> 3) * MDIM + cta * CELLS + (tid & 7);
        xg_c = __ldcg(xr);
        if (tid < 8) ux_c = __ldcg(xr + 4 * MDIM);
    }

    for (int t = 0; t < T_STEPS; t++) {
        const unsigned useIdx  = epoch * 1024u + (unsigned)(t >> 3) + 1u;
        unsigned* const ctrA   = g_ctrA + (t & 7) * 32;
        unsigned* const ctrH   = g_ctrH + (t & 7) * 32;
        const unsigned targetA = useIdx << 8;   // 256 arrivals per use
        const unsigned targetH = useIdx << 7;   // 128 arrivals per use

        // stage this step's xproj values to smem; issue next step's loads
        if (tid < 32) {
            xg_s[tid] = xg_c;
            if (tid < 8) gu_s[tid] = ux_c;
            int tn = (t + 1 < T_STEPS) ? t + 1 : t;
            const float* xr = g_xproj + (size_t)tn * XCOLS + (tid >> 3) * MDIM + cta * CELLS + (tid & 7);
            xg_c = __ldcg(xr);
            if (tid < 8) ux_c = __ldcg(xr + 4 * MDIM);
        }

        // ---------- Phase A: hp = Wh @ h + bh (h synced by step t-1's barrier)
        float acc0 = 0.f, acc1 = 0.f, acc2 = 0.f, acc3 = 0.f;
        if (t > 0) {
            ((float4*)h_s)[tid] = __ldcg(gh4 + tid);
            __syncthreads();
#pragma unroll
            for (int c4 = 0; c4 < 8; c4++) {
                float4 hv = ((const float4*)h_s)[c4 * 32 + l];
                acc0 += wa[0][c4].x * hv.x + wa[0][c4].y * hv.y + wa[0][c4].z * hv.z + wa[0][c4].w * hv.w;
                acc1 += wa[1][c4].x * hv.x + wa[1][c4].y * hv.y + wa[1][c4].z * hv.z + wa[1][c4].w * hv.w;
                acc2 += wa[2][c4].x * hv.x + wa[2][c4].y * hv.y + wa[2][c4].z * hv.z + wa[2][c4].w * hv.w;
                acc3 += wa[3][c4].x * hv.x + wa[3][c4].y * hv.y + wa[3][c4].z * hv.z + wa[3][c4].w * hv.w;
            }
#pragma unroll
            for (int off = 16; off > 0; off >>= 1) {
                acc0 += __shfl_xor_sync(0xffffffffu, acc0, off);
                acc1 += __shfl_xor_sync(0xffffffffu, acc1, off);
                acc2 += __shfl_xor_sync(0xffffffffu, acc2, off);
                acc3 += __shfl_xor_sync(0xffffffffu, acc3, off);
            }
        } else {
            __syncthreads();   // cover xg_s/gu_s writes at t==0
        }

        // ---------- gates in-warp; z-warps publish a + arrive ----------------
        if (l < 4) {
            float av = acc0;
            if (l == 1) av = acc1; else if (l == 2) av = acc2; else if (l == 3) av = acc3;
            int s = 4 * w + l;
            float hpv = __fadd_rn(av, bh_s[s]);         // t==0: 0+bh == bh
            float gv  = xla_sigmoid(__fadd_rn(xg_s[s], hpv));
            if ((unsigned)(w - 4) < 2u) {               // z-gate rows (16..23)
                int cell = s & 7;
                __stcg(&g_a[cta * CELLS + cell], __fmul_rn(gv, tc_s[cell]));
            } else {
                gate_s[s] = gv;                         // i/o/f for phase B
            }
        }
        if ((unsigned)(w - 4) < 2u) {
            __syncwarp();
            if (l == 0) red_rel(ctrA);                  // 2 arrivals per CTA
        }
        if (tid == 0) { while (ld_acq(ctrA) < targetA) { } }
        __syncthreads();

        // ---------- Phase B: u = tanh(ux + Wm@a + bm); state update ----------
        ((float4*)a_s)[tid] = __ldcg(ga4 + tid);
        __syncthreads();
        float acc = 0.f;
#pragma unroll
        for (int c4 = 0; c4 < 8; c4++) {
            float4 av = ((const float4*)a_s)[c4 * 32 + l];
            acc += wmr[c4].x * av.x + wmr[c4].y * av.y + wmr[c4].z * av.z + wmr[c4].w * av.w;
        }
#pragma unroll
        for (int off = 16; off > 0; off >>= 1)
            acc += __shfl_xor_sync(0xffffffffu, acc, off);

        if (l == 0) {
            float u  = xla_tanh(__fadd_rn(__fadd_rn(gu_s[w], acc), bm_s[w]));
            float c2 = __fadd_rn(__fmul_rn(gate_s[w], u), __fmul_rn(gate_s[24 + w], c_s[w]));
            float th = xla_tanh(c2);
            float h2 = __fmul_rn(gate_s[8 + w], th);
            c_s[w]  = c2;
            tc_s[w] = th;    // reused next step: a = z * tanh(c)
            if (t == T_STEPS - 1) {
                out[cta * CELLS + w]        = c2;
                out[MDIM + cta * CELLS + w] = h2;
            } else {
                __stcg(&g_h[cta * CELLS + w], h2);
            }
        }
        __syncthreads();     // order h stores before the release arrival
        if (tid == 0) {
            red_rel(ctrH);                              // uniform: every step
            while (ld_acq(ctrH) < targetH) { }
        }
        __syncthreads();
    }

    // one epoch bump per launch (every CTA read g_epoch before its first
    // barrier; replays are stream-ordered; counters stay monotonic, no resets)
    if (cta == 0 && tid == 0)
        asm volatile("red.relaxed.gpu.global.add.u32 [%0], 1;" :: "l"(&g_epoch) : "memory");
}

// ---------------- launch ------------------------------------------------------
extern "C" void kernel_launch(void* const* d_in, const int* in_sizes, int n_in,
                              void* d_out, int out_size)
{
    const float* inputs = (const float*)d_in[0];
    const float* Wx     = (const float*)d_in[1];
    const float* bx     = (const float*)d_in[2];
    const float* Wh     = (const float*)d_in[3];
    const float* bh     = (const float*)d_in[4];
    const float* Wm     = (const float*)d_in[5];
    const float* bm     = (const float*)d_in[6];
    float* out = (float*)d_out;

    dim3 ggrid(XCOLS / 128, T_STEPS / 128);   // (40, 64)
    xproj_gemm<<<ggrid, 256>>>(inputs, Wx, bx);

    ulstm_scan<<<NCTA, NTHR>>>(Wh, bh, Wm, bm, out);
}

// round 16
// speedup vs baseline: 2.6596x; 1.2704x over previous
#include <cuda_runtime.h>

#define T_STEPS 8192
#define MDIM    1024
#define INDIM   1024
#define XCOLS   5120
#define NCTA    128
#define NTHR    256
#define CELLS   8      // memory cells owned per CTA (1024/128)

// ---------------- scratch (static device globals; no allocation) -------------
__device__ float    g_xproj[(size_t)T_STEPS * XCOLS];   // 160 MB
__device__ float    g_h[MDIM];                           // h broadcast payload
__device__ float    g_a[MDIM];                           // a broadcast payload
__device__ unsigned g_ctr[2 * T_STEPS];                  // one slot per barrier (R7-proven)
__device__ unsigned g_epoch;                             // completed scan launches

// ---- R7-proven barrier primitives ---------------------------------------------
__device__ __forceinline__ void bar_arrive(unsigned slot) {
    asm volatile("red.release.gpu.global.add.u32 [%0], 1;"
                 :: "l"(&g_ctr[slot]) : "memory");
}
__device__ __forceinline__ void bar_wait(unsigned slot, unsigned target) {
    unsigned v;
    do {
        asm volatile("ld.acquire.gpu.global.u32 %0, [%1];"
                     : "=r"(v) : "l"(&g_ctr[slot]) : "memory");
    } while (v < target);
}

// ---- XLA-matched transcendentals ---------------------------------------------
__device__ __forceinline__ float xla_tanh(float x) {
    float xc = fminf(fmaxf(x, -9.0f), 9.0f);
    float x2 = xc * xc;
    float p = fmaf(x2, -2.76076847742355e-16f, 2.00018790482477e-13f);
    p = fmaf(x2, p, -8.60467152213735e-11f);
    p = fmaf(x2, p,  5.12229709037114e-08f);
    p = fmaf(x2, p,  1.48572235717979e-05f);
    p = fmaf(x2, p,  6.37261928875436e-04f);
    p = fmaf(x2, p,  4.89352455891786e-03f);
    float num = __fmul_rn(xc, p);
    float q = fmaf(x2, 1.19825839466702e-06f, 1.18534705686654e-04f);
    q = fmaf(x2, q, 2.26843463243900e-03f);
    q = fmaf(x2, q, 4.89352518554385e-03f);
    return (fabsf(x) < 4.0e-4f) ? x : __fdiv_rn(num, q);
}
__device__ __forceinline__ float xla_sigmoid(float x) {
    float e;
    asm("ex2.approx.f32 %0, %1;" : "=f"(e) : "f"(-x * 1.4426950408889634f));
    return __fdiv_rn(1.0f, __fadd_rn(1.0f, e));
}

// ---------------- Kernel 1: xproj = inputs @ Wx^T + bx  (NT SGEMM, fp32) -----
__global__ void __launch_bounds__(256) xproj_gemm(
    const float* __restrict__ A,
    const float* __restrict__ B,
    const float* __restrict__ bias)
{
    __shared__ float As[8][128];
    __shared__ float Bs[8][128];

    int tid = threadIdx.x;
    int tx  = tid & 15, ty = tid >> 4;
    int m0  = blockIdx.y * 128, n0 = blockIdx.x * 128;
    int lrow = tid >> 1, lk = (tid & 1) * 4;

    const float* Ap = A + (size_t)(m0 + lrow) * INDIM + lk;
    const float* Bp = B + (size_t)(n0 + lrow) * INDIM + lk;

    float acc[8][8];
#pragma unroll
    for (int i = 0; i < 8; i++)
#pragma unroll
        for (int j = 0; j < 8; j++) acc[i][j] = 0.0f;

    for (int k0 = 0; k0 < INDIM; k0 += 8) {
        float4 av = *(const float4*)(Ap + k0);
        float4 bv = *(const float4*)(Bp + k0);
        As[lk + 0][lrow] = av.x; As[lk + 1][lrow] = av.y;
        As[lk + 2][lrow] = av.z; As[lk + 3][lrow] = av.w;
        Bs[lk + 0][lrow] = bv.x; Bs[lk + 1][lrow] = bv.y;
        Bs[lk + 2][lrow] = bv.z; Bs[lk + 3][lrow] = bv.w;
        __syncthreads();
#pragma unroll
        for (int kk = 0; kk < 8; kk++) {
            float a[8], b[8];
            *(float4*)&a[0] = *(const float4*)&As[kk][ty * 8];
            *(float4*)&a[4] = *(const float4*)&As[kk][ty * 8 + 4];
            *(float4*)&b[0] = *(const float4*)&Bs[kk][tx * 8];
            *(float4*)&b[4] = *(const float4*)&Bs[kk][tx * 8 + 4];
#pragma unroll
            for (int i = 0; i < 8; i++)
#pragma unroll
                for (int j = 0; j < 8; j++) acc[i][j] += a[i] * b[j];
        }
        __syncthreads();
    }

    float bb[8];
#pragma unroll
    for (int j = 0; j < 8; j++) bb[j] = bias[n0 + tx * 8 + j];
#pragma unroll
    for (int i = 0; i < 8; i++) {
        float* crow = g_xproj + (size_t)(m0 + ty * 8 + i) * XCOLS + n0 + tx * 8;
        float4 v0 = make_float4(__fadd_rn(acc[i][0], bb[0]), __fadd_rn(acc[i][1], bb[1]),
                                __fadd_rn(acc[i][2], bb[2]), __fadd_rn(acc[i][3], bb[3]));
        float4 v1 = make_float4(__fadd_rn(acc[i][4], bb[4]), __fadd_rn(acc[i][5], bb[5]),
                                __fadd_rn(acc[i][6], bb[6]), __fadd_rn(acc[i][7], bb[7]));
        *(float4*)crow       = v0;
        *(float4*)(crow + 4) = v1;
    }
}

// ---------------- Kernel 2: persistent recurrent scan ------------------------
// 128 CTAs x 256 threads, R7 barrier. Warp w owns CELL w entirely:
// Wh rows {z,i,o,f} x cell w (wa[0..3]) and Wm row w. z-row computed FIRST so
// `a` publishes before i/o/f rows, which overlap the A-barrier settle.
__global__ void __launch_bounds__(NTHR, 1) ulstm_scan(
    const float* __restrict__ Wh, const float* __restrict__ bh,
    const float* __restrict__ Wm, const float* __restrict__ bm,
    float* __restrict__ out)
{
    __shared__ __align__(16) float h_s[MDIM];
    __shared__ __align__(16) float a_s[MDIM];

    const int tid = threadIdx.x;
    const int w   = tid >> 5;
    const int l   = tid & 31;
    const int cta = blockIdx.x;
    const int cw  = cta * CELLS + w;   // this warp's cell (global index)

    const unsigned target = (*((volatile unsigned*)&g_epoch) + 1u) * (unsigned)NCTA;

    // ---- weights into registers: wa[0]=z-row, wa[1]=i, wa[2]=o, wa[3]=f ----
    float4 wa[4][8];
    {
        const int gorder[4] = {2, 0, 1, 3};   // gate memory order: i,o,z,f
#pragma unroll
        for (int r = 0; r < 4; r++) {
            const float4* src = (const float4*)(Wh + (size_t)(gorder[r] * MDIM + cw) * MDIM);
#pragma unroll
            for (int c4 = 0; c4 < 8; c4++) wa[r][c4] = src[c4 * 32 + l];
        }
    }
    float4 wmr[8];
    {
        const float4* src = (const float4*)(Wm + (size_t)cw * MDIM);
#pragma unroll
        for (int c4 = 0; c4 < 8; c4++) wmr[c4] = src[c4 * 32 + l];
    }
    // lane-0 per-cell scalars (cell w state lives in warp w)
    float bhz = 0.f, bhi = 0.f, bho = 0.f, bhf = 0.f, bmw = 0.f;
    float c_r = 0.f, tc_r = 0.f;
    if (l == 0) {
        bhi = bh[cw];            bho = bh[MDIM + cw];
        bhz = bh[2 * MDIM + cw]; bhf = bh[3 * MDIM + cw];
        bmw = bm[cw];
    }
    // xproj prefetch: lane g (g<5) of warp w holds gate g for cell w, one step ahead
    float xg_pre = 0.f;
    if (l < 5) xg_pre = __ldcg(g_xproj + (size_t)l * MDIM + cw);
    __syncthreads();

    const float4* gh4 = (const float4*)g_h;
    const float4* ga4 = (const float4*)g_a;

    for (int t = 0; t < T_STEPS; t++) {
        const float xg_use = xg_pre;
        if (l < 5) {
            int tn = (t + 1 < T_STEPS) ? t + 1 : t;
            xg_pre = __ldcg(g_xproj + (size_t)tn * XCOLS + (size_t)l * MDIM + cw);
        }
        // prefetch the barrier counter line ~32 steps ahead (kills cold-L2 spikes)
        if (tid == 32) {
            int pf = 2 * t + 64;
            if (pf < 2 * T_STEPS) {
                unsigned tmp;
                asm volatile("ld.global.cg.u32 %0, [%1];" : "=r"(tmp) : "l"(&g_ctr[pf]));
            }
        }

        // ---------- h -> smem ----------
        if (t > 0) ((float4*)h_s)[tid] = __ldcg(gh4 + tid);
        __syncthreads();

        // ---------- z-row dot FIRST; publish a; arrive ----------
        float dz = 0.f;
        if (t > 0) {
#pragma unroll
            for (int c4 = 0; c4 < 8; c4++) {
                float4 hv = ((const float4*)h_s)[c4 * 32 + l];
                dz += wa[0][c4].x * hv.x + wa[0][c4].y * hv.y + wa[0][c4].z * hv.z + wa[0][c4].w * hv.w;
            }
#pragma unroll
            for (int off = 16; off > 0; off >>= 1)
                dz += __shfl_xor_sync(0xffffffffu, dz, off);
        }
        float zx = __shfl_sync(0xffffffffu, xg_use, 2);
        if (l == 0) {
            float hpz = __fadd_rn(dz, bhz);                       // t==0: 0+bh == bh
            float z   = xla_sigmoid(__fadd_rn(zx, hpz));
            __stcg(&g_a[cw], __fmul_rn(z, tc_r));
        }
        __syncthreads();
        if (tid == 0) bar_arrive(2 * t);

        // ---------- i/o/f rows (overlap the A-barrier settle) ----------
        float d0 = 0.f, d1 = 0.f, d2 = 0.f;
        if (t > 0) {
#pragma unroll
            for (int c4 = 0; c4 < 8; c4++) {
                float4 hv = ((const float4*)h_s)[c4 * 32 + l];
                d0 += wa[1][c4].x * hv.x + wa[1][c4].y * hv.y + wa[1][c4].z * hv.z + wa[1][c4].w * hv.w;
                d1 += wa[2][c4].x * hv.x + wa[2][c4].y * hv.y + wa[2][c4].z * hv.z + wa[2][c4].w * hv.w;
                d2 += wa[3][c4].x * hv.x + wa[3][c4].y * hv.y + wa[3][c4].z * hv.z + wa[3][c4].w * hv.w;
            }
#pragma unroll
            for (int off = 16; off > 0; off >>= 1) {
                d0 += __shfl_xor_sync(0xffffffffu, d0, off);
                d1 += __shfl_xor_sync(0xffffffffu, d1, off);
                d2 += __shfl_xor_sync(0xffffffffu, d2, off);
            }
        }
        float ix_ = __shfl_sync(0xffffffffu, xg_use, 0);
        float ox_ = __shfl_sync(0xffffffffu, xg_use, 1);
        float fx_ = __shfl_sync(0xffffffffu, xg_use, 3);
        float ux_ = __shfl_sync(0xffffffffu, xg_use, 4);
        float gi = 0.f, go = 0.f, gf = 0.f;
        if (l == 0) {
            gi = xla_sigmoid(__fadd_rn(ix_, __fadd_rn(d0, bhi)));
            go = xla_sigmoid(__fadd_rn(ox_, __fadd_rn(d1, bho)));
            gf = xla_sigmoid(__fadd_rn(fx_, __fadd_rn(d2, bhf)));
        }
        if (tid == 0) bar_wait(2 * t, target);
        __syncthreads();

        // ---------- Phase B: u = tanh(ux + Wm@a + bm); state update ----------
        ((float4*)a_s)[tid] = __ldcg(ga4 + tid);
        __syncthreads();
        float acc = 0.f;
#pragma unroll
        for (int c4 = 0; c4 < 8; c4++) {
            float4 av = ((const float4*)a_s)[c4 * 32 + l];
            acc += wmr[c4].x * av.x + wmr[c4].y * av.y + wmr[c4].z * av.z + wmr[c4].w * av.w;
        }
#pragma unroll
        for (int off = 16; off > 0; off >>= 1)
            acc += __shfl_xor_sync(0xffffffffu, acc, off);

        if (l == 0) {
            float u  = xla_tanh(__fadd_rn(__fadd_rn(ux_, acc), bmw));
            float c2 = __fadd_rn(__fmul_rn(gi, u), __fmul_rn(gf, c_r));
            float th = xla_tanh(c2);
            float h2 = __fmul_rn(go, th);
            c_r  = c2;
            tc_r = th;    // reused next step: a = z * tanh(c)
            if (t == T_STEPS - 1) {
                out[cw]        = c2;
                out[MDIM + cw] = h2;
            } else {
                __stcg(&g_h[cw], h2);
            }
        }
        __syncthreads();   // order all warps' h stores before the release arrival
        if (t < T_STEPS - 1) {
            if (tid == 0) {
                bar_arrive(2 * t + 1);
                bar_wait(2 * t + 1, target);
            }
            __syncthreads();
        }
    }

    // one epoch bump per launch (every CTA read g_epoch before its first
    // barrier; replays are stream-ordered; counters stay monotonic, no resets)
    if (cta == 0 && tid == 0)
        asm volatile("red.relaxed.gpu.global.add.u32 [%0], 1;" :: "l"(&g_epoch) : "memory");
}

// ---------------- launch ------------------------------------------------------
extern "C" void kernel_launch(void* const* d_in, const int* in_sizes, int n_in,
                              void* d_out, int out_size)
{
    const float* inputs = (const float*)d_in[0];
    const float* Wx     = (const float*)d_in[1];
    const float* bx     = (const float*)d_in[2];
    const float* Wh     = (const float*)d_in[3];
    const float* bh     = (const float*)d_in[4];
    const float* Wm     = (const float*)d_in[5];
    const float* bm     = (const float*)d_in[6];
    float* out = (float*)d_out;

    dim3 ggrid(XCOLS / 128, T_STEPS / 128);   // (40, 64)
    xproj_gemm<<<ggrid, 256>>>(inputs, Wx, bx);

    ulstm_scan<<<NCTA, NTHR>>>(Wh, bh, Wm, bm, out);
}